// round 7
// baseline (speedup 1.0000x reference)
#include <cuda_runtime.h>
#include <cstdint>
#include <math.h>

// ---------------------------------------------------------------------------
// Order1GraphAttentionLayer  (B=4, N=4096, D=256)
//   Ax = feat @ (W@a1)   Ay = feat @ (W@a2)
//   P[i,j] = adj ? ( (Ax[j]+Ay[i])>0 ? e^Ax[j] e^Ay[i] : e^{.2Ax[j]} e^{.2Ay[i]} ) : 0
//   h' = (P @ feat) / rowsum(P)           <- tf32 tensor-core GEMM
//   out = ELU( h' @ W )                   <- fp32 epilogue GEMM
// ---------------------------------------------------------------------------

#define ALPHA  0.2f
#define NB     4
#define NN     4096
#define DDIM   256
#define IT     128                 // i-rows per CTA
#define JT     32                  // j (K) chunk
#define NCHUNK (NN / JT)           // 128
#define MAIN_THREADS 512
#define FSTR   264                 // feat smem row stride (floats), conflict-free B frags
#define PSTR   36                  // P smem row stride (floats), conflict-free A frags

// main-kernel shared memory layout (float offsets)
#define S_AX   0                       // 4096  Ax[j]      (sign test)
#define S_EX   4096                    // 4096  exp(Ax[j])
#define S_EX5  8192                    // 4096  exp(.2Ax[j])
#define S_FB   12288                   // 2 * 32*264 = 16896 feat double buffer
#define S_PB   (12288 + 16896)         // 2 * 128*36 = 9216  P double buffer
#define S_RS   (S_PB + 9216)           // 128   1/rowsum
#define MAIN_SMEM_FLOATS (S_RS + 128)  // 38528
#define MAIN_SMEM_BYTES  (MAIN_SMEM_FLOATS * 4)   // 154112 B

#define EP_THREADS 256
#define EP_ROWS    32
#define EP_SMEM_BYTES ((32 * 256 + 64 * 256) * 4)  // 98304 B

// ---------------- device scratch (allocation-free rule: __device__ globals) --
__device__ float g_featr[(size_t)NB * NN * DDIM];  // feat rounded to tf32 (rna)
__device__ float g_hp   [(size_t)NB * NN * DDIM];  // normalized h'
__device__ float g_wa1[DDIM];
__device__ float g_wa2[DDIM];
__device__ float g_Ax  [NB * NN];
__device__ float g_Ay  [NB * NN];
__device__ float g_exj [NB * NN];   // exp(Ax)
__device__ float g_exj5[NB * NN];   // exp(.2 Ax)
__device__ float g_eyi [NB * NN];   // exp(Ay)
__device__ float g_eyi5[NB * NN];   // exp(.2 Ay)

__device__ __forceinline__ float tf32r(float x) {
    unsigned int u;
    asm("cvt.rna.tf32.f32 %0, %1;" : "=r"(u) : "f"(x));
    return __uint_as_float(u);
}

// ---------------- K1: wa1 = W@a1, wa2 = W@a2 --------------------------------
__global__ void prep_w_kernel(const float* __restrict__ W,
                              const float* __restrict__ a1,
                              const float* __restrict__ a2) {
    int r = blockIdx.x;           // output row 0..255
    int j = threadIdx.x;          // 0..255
    float w  = W[r * DDIM + j];
    float p1 = w * a1[j];
    float p2 = w * a2[j];
    #pragma unroll
    for (int o = 16; o; o >>= 1) {
        p1 += __shfl_xor_sync(0xffffffffu, p1, o);
        p2 += __shfl_xor_sync(0xffffffffu, p2, o);
    }
    __shared__ float s1[8], s2[8];
    int wrp = j >> 5, ln = j & 31;
    if (ln == 0) { s1[wrp] = p1; s2[wrp] = p2; }
    __syncthreads();
    if (j == 0) {
        float t1 = 0.f, t2 = 0.f;
        #pragma unroll
        for (int k = 0; k < 8; k++) { t1 += s1[k]; t2 += s2[k]; }
        g_wa1[r] = t1;
        g_wa2[r] = t2;
    }
}

// ---------------- K2: per-node Ax/Ay dots, exp arrays, feat->tf32 copy ------
__global__ void prep_nodes_kernel(const float* __restrict__ feat) {
    __shared__ float w1s[DDIM], w2s[DDIM];
    int tid = threadIdx.x;
    if (tid < DDIM) { w1s[tid] = g_wa1[tid]; w2s[tid] = g_wa2[tid]; }
    __syncthreads();
    int row = blockIdx.x * 8 + (tid >> 5);   // 2048 blocks * 8 warps -> 16384 rows
    int ln  = tid & 31;
    size_t base = (size_t)row * DDIM + ln * 8;
    float4 v0 = *(const float4*)(feat + base);
    float4 v1 = *(const float4*)(feat + base + 4);
    const float* w1 = w1s + ln * 8;
    const float* w2 = w2s + ln * 8;
    float s1 = v0.x * w1[0] + v0.y * w1[1] + v0.z * w1[2] + v0.w * w1[3]
             + v1.x * w1[4] + v1.y * w1[5] + v1.z * w1[6] + v1.w * w1[7];
    float s2 = v0.x * w2[0] + v0.y * w2[1] + v0.z * w2[2] + v0.w * w2[3]
             + v1.x * w2[4] + v1.y * w2[5] + v1.z * w2[6] + v1.w * w2[7];
    float4 r0, r1;
    r0.x = tf32r(v0.x); r0.y = tf32r(v0.y); r0.z = tf32r(v0.z); r0.w = tf32r(v0.w);
    r1.x = tf32r(v1.x); r1.y = tf32r(v1.y); r1.z = tf32r(v1.z); r1.w = tf32r(v1.w);
    *(float4*)(g_featr + base)     = r0;
    *(float4*)(g_featr + base + 4) = r1;
    #pragma unroll
    for (int o = 16; o; o >>= 1) {
        s1 += __shfl_xor_sync(0xffffffffu, s1, o);
        s2 += __shfl_xor_sync(0xffffffffu, s2, o);
    }
    if (ln == 0) {
        g_Ax  [row] = s1;
        g_exj [row] = expf(s1);
        g_exj5[row] = expf(ALPHA * s1);
        g_Ay  [row] = s2;
        g_eyi [row] = expf(s2);
        g_eyi5[row] = expf(ALPHA * s2);
    }
}

// ---------------- K3: main fused kernel — P gen + tf32 mma P@feat -----------
__global__ __launch_bounds__(MAIN_THREADS, 1)
void gat_main_kernel(const int* __restrict__ adj) {
    extern __shared__ float sm[];
    int tid  = threadIdx.x;
    int b    = blockIdx.x >> 5;            // 32 CTAs per batch
    int i0   = (blockIdx.x & 31) * IT;
    int wrp  = tid >> 5;
    int lane = tid & 31;

    // --- preload j-side arrays for this batch (48 KB) ---
    {
        const float* pax  = g_Ax   + b * NN;
        const float* pex  = g_exj  + b * NN;
        const float* pex5 = g_exj5 + b * NN;
        for (int i = tid; i < NN; i += MAIN_THREADS) {
            sm[S_AX  + i] = pax[i];
            sm[S_EX  + i] = pex[i];
            sm[S_EX5 + i] = pex5[i];
        }
    }
    // --- row-side (fixed per thread for P generation) ---
    int r  = tid >> 2;        // 0..127  (row within i-tile)
    int cg = tid & 3;         // col group: j-cols cg*8 .. cg*8+7
    float rAy  = g_Ay  [b * NN + i0 + r];
    float rey  = g_eyi [b * NN + i0 + r];
    float rey5 = g_eyi5[b * NN + i0 + r];

    const int*   adjbase = adj + (((size_t)(b * NN + i0 + r)) << 12) + cg * 8;
    const float* fgbase  = g_featr + (size_t)b * NN * DDIM;

    float acc[16][4];
    #pragma unroll
    for (int nt = 0; nt < 16; nt++) {
        acc[nt][0] = 0.f; acc[nt][1] = 0.f; acc[nt][2] = 0.f; acc[nt][3] = 0.f;
    }
    float rsum = 0.f;
    float4 fr[4];
    int4   ar[2];

#define LOADG(c) do {                                                          \
        int j0_ = (c) * JT;                                                    \
        const float4* src_ = (const float4*)(fgbase + (size_t)j0_ * DDIM);     \
        fr[0] = src_[tid];                                                     \
        fr[1] = src_[tid +     MAIN_THREADS];                                  \
        fr[2] = src_[tid + 2 * MAIN_THREADS];                                  \
        fr[3] = src_[tid + 3 * MAIN_THREADS];                                  \
        const int4* ap_ = (const int4*)(adjbase + j0_);                        \
        ar[0] = ap_[0];                                                        \
        ar[1] = ap_[1];                                                        \
    } while (0)

#define GENP(c, buf) do {                                                      \
        int j0_ = (c) * JT;                                                    \
        float pq_[8];                                                          \
        _Pragma("unroll")                                                      \
        for (int q = 0; q < 8; q++) {                                          \
            int av_ = (q < 4) ? ((const int*)&ar[0])[q]                        \
                              : ((const int*)&ar[1])[q - 4];                   \
            int j_  = j0_ + cg * 8 + q;                                        \
            float lg_ = sm[S_AX + j_] + rAy;                                   \
            float e_  = (lg_ > 0.f) ? sm[S_EX + j_] * rey                      \
                                    : sm[S_EX5 + j_] * rey5;                   \
            float p_  = (av_ > 0) ? e_ : 0.f;                                  \
            p_ = tf32r(p_);                                                    \
            pq_[q] = p_;                                                       \
            rsum += p_;                                                        \
        }                                                                      \
        float* pb_ = sm + S_PB + (buf) * (IT * PSTR) + r * PSTR + cg * 8;      \
        *(float4*)(pb_)     = make_float4(pq_[0], pq_[1], pq_[2], pq_[3]);     \
        *(float4*)(pb_ + 4) = make_float4(pq_[4], pq_[5], pq_[6], pq_[7]);     \
        float* fb_ = sm + S_FB + (buf) * (JT * FSTR);                          \
        _Pragma("unroll")                                                      \
        for (int k = 0; k < 4; k++) {                                          \
            int f_    = tid + k * MAIN_THREADS;                                \
            int rowj_ = f_ >> 6;                                               \
            int col_  = (f_ & 63) << 2;                                        \
            *(float4*)(fb_ + rowj_ * FSTR + col_) = fr[k];                     \
        }                                                                      \
    } while (0)

#define MMACHUNK(buf) do {                                                     \
        const float* pbF_ = sm + S_PB + (buf) * (IT * PSTR);                   \
        const float* fbF_ = sm + S_FB + (buf) * (JT * FSTR);                   \
        int g_  = lane >> 2;                                                   \
        int tg_ = lane & 3;                                                    \
        int mb_ = (wrp >> 1) * 16;                                             \
        int nb_ = (wrp & 1) * 128;                                             \
        _Pragma("unroll")                                                      \
        for (int ks = 0; ks < 4; ks++) {                                       \
            const unsigned int* pa_ = (const unsigned int*)                    \
                (pbF_ + (mb_ + g_) * PSTR + ks * 8 + tg_);                     \
            unsigned int a0_ = pa_[0];                                         \
            unsigned int a1_ = pa_[8 * PSTR];                                  \
            unsigned int a2_ = pa_[4];                                         \
            unsigned int a3_ = pa_[8 * PSTR + 4];                              \
            const unsigned int* pbb_ = (const unsigned int*)                   \
                (fbF_ + (ks * 8 + tg_) * FSTR + nb_ + g_);                     \
            _Pragma("unroll")                                                  \
            for (int nt = 0; nt < 16; nt++) {                                  \
                unsigned int b0_ = pbb_[nt * 8];                               \
                unsigned int b1_ = pbb_[nt * 8 + 4 * FSTR];                    \
                asm volatile(                                                  \
                  "mma.sync.aligned.m16n8k8.row.col.f32.tf32.tf32.f32 "        \
                  "{%0,%1,%2,%3}, {%4,%5,%6,%7}, {%8,%9}, {%0,%1,%2,%3};\n"   \
                  : "+f"(acc[nt][0]), "+f"(acc[nt][1]),                        \
                    "+f"(acc[nt][2]), "+f"(acc[nt][3])                         \
                  : "r"(a0_), "r"(a1_), "r"(a2_), "r"(a3_),                    \
                    "r"(b0_), "r"(b1_));                                       \
            }                                                                  \
        }                                                                      \
    } while (0)

    // --- software pipeline: LDG(c+1) | mma(c) | P-gen/STS(c+1) | bar ---
    LOADG(0);
    GENP(0, 0);
    __syncthreads();
    for (int c = 0; c < NCHUNK; c++) {
        int cur = c & 1;
        if (c + 1 < NCHUNK) LOADG(c + 1);
        MMACHUNK(cur);
        if (c + 1 < NCHUNK) GENP(c + 1, cur ^ 1);
        __syncthreads();
    }
#undef LOADG
#undef GENP
#undef MMACHUNK

    // --- rowsum reduce (4 threads per row, same warp) ---
    rsum += __shfl_xor_sync(0xffffffffu, rsum, 1);
    rsum += __shfl_xor_sync(0xffffffffu, rsum, 2);
    if (cg == 0) sm[S_RS + r] = 1.0f / rsum;
    __syncthreads();

    // --- scale by 1/rowsum and store h' ---
    {
        int g_  = lane >> 2;
        int tg_ = lane & 3;
        int mb_ = (wrp >> 1) * 16;
        int nb_ = (wrp & 1) * 128;
        float inv0 = sm[S_RS + mb_ + g_];
        float inv1 = sm[S_RS + mb_ + g_ + 8];
        float* hp0 = g_hp + (size_t)(b * NN + i0 + mb_ + g_) * DDIM;
        #pragma unroll
        for (int nt = 0; nt < 16; nt++) {
            int col = nb_ + nt * 8 + tg_ * 2;
            *(float2*)(hp0 + col) =
                make_float2(acc[nt][0] * inv0, acc[nt][1] * inv0);
            *(float2*)(hp0 + 8 * DDIM + col) =
                make_float2(acc[nt][2] * inv1, acc[nt][3] * inv1);
        }
    }
}

// ---------------- K4: epilogue — out = ELU(h' @ W) --------------------------
__global__ __launch_bounds__(EP_THREADS)
void gat_epilogue_kernel(const float* __restrict__ W, float* __restrict__ out) {
    extern __shared__ float es[];
    float* hs = es;            // 32 x 256
    float* Ws = es + 8192;     // 64 x 256 (K chunk)
    int tid  = threadIdx.x;
    int wrp  = tid >> 5;
    int lane = tid & 31;
    int R0   = blockIdx.x * EP_ROWS;

    {   // stage h' rows
        const float4* src = (const float4*)(g_hp + (size_t)R0 * DDIM);
        float4* dst = (float4*)hs;
        #pragma unroll
        for (int k = 0; k < 8; k++)
            dst[tid + k * EP_THREADS] = src[tid + k * EP_THREADS];
    }

    float acc[4][8];
    #pragma unroll
    for (int s = 0; s < 4; s++)
        #pragma unroll
        for (int q = 0; q < 8; q++) acc[s][q] = 0.f;

    for (int kc = 0; kc < 4; kc++) {
        __syncthreads();
        const float4* wsrc = (const float4*)(W + kc * 64 * DDIM);
        float4* wdst = (float4*)Ws;
        #pragma unroll
        for (int k = 0; k < 16; k++)
            wdst[tid + k * EP_THREADS] = wsrc[tid + k * EP_THREADS];
        __syncthreads();
        for (int k = 0; k < 64; k++) {
            float wv[8];
            #pragma unroll
            for (int q = 0; q < 8; q++)
                wv[q] = Ws[k * DDIM + lane + 32 * q];   // conflict-free
            #pragma unroll
            for (int s = 0; s < 4; s++) {
                float h = hs[(wrp + 8 * s) * DDIM + kc * 64 + k];  // broadcast
                #pragma unroll
                for (int q = 0; q < 8; q++) acc[s][q] += h * wv[q];
            }
        }
    }
    #pragma unroll
    for (int s = 0; s < 4; s++) {
        int row = R0 + wrp + 8 * s;
        float* op = out + (size_t)row * DDIM;
        #pragma unroll
        for (int q = 0; q < 8; q++) {
            float v = acc[s][q];
            op[lane + 32 * q] = (v > 0.f) ? v : (expf(v) - 1.0f);
        }
    }
}

// ---------------------------------------------------------------------------
extern "C" void kernel_launch(void* const* d_in, const int* in_sizes, int n_in,
                              void* d_out, int out_size) {
    const float* feat = (const float*)d_in[0];
    const int*   adj  = (const int*)d_in[1];
    const float* W    = (const float*)d_in[2];
    const float* a1   = (const float*)d_in[3];
    const float* a2   = (const float*)d_in[4];
    float* out = (float*)d_out;

    cudaFuncSetAttribute(gat_main_kernel,
                         cudaFuncAttributeMaxDynamicSharedMemorySize,
                         MAIN_SMEM_BYTES);
    cudaFuncSetAttribute(gat_epilogue_kernel,
                         cudaFuncAttributeMaxDynamicSharedMemorySize,
                         EP_SMEM_BYTES);

    prep_w_kernel    <<<256, 256>>>(W, a1, a2);
    prep_nodes_kernel<<<2048, 256>>>(feat);
    gat_main_kernel  <<<NB * (NN / IT), MAIN_THREADS, MAIN_SMEM_BYTES>>>(adj);
    gat_epilogue_kernel<<<(NB * NN) / EP_ROWS, EP_THREADS, EP_SMEM_BYTES>>>(W, out);
    (void)in_sizes; (void)n_in; (void)out_size;
}

// round 8
// speedup vs baseline: 1.7429x; 1.7429x over previous
#include <cuda_runtime.h>
#include <cstdint>
#include <math.h>

// ---------------------------------------------------------------------------
// GAT layer (B=4, N=4096, D=256)
//   wa1=W@a1, wa2=W@a2; Ax=feat@wa1, Ay=feat@wa2 (fp32 exact)
//   h = feat@W   (tf32x3 tensor GEMM, ~fp32 accurate, stored tf32)
//   P[i,j] = adj ? (Ax[j]+Ay[i]>0 ? e^Ax[j]e^Ay[i] : e^{.2Ax[j]}e^{.2Ay[i]}) : 0
//   out = ELU( (P @ h) / rowsum(P) )   (tf32 tensor GEMM, fused epilogue)
// ---------------------------------------------------------------------------

#define ALPHA  0.2f
#define NB     4
#define NN     4096
#define DDIM   256
#define IT     128
#define JT     32
#define NCHUNK (NN / JT)
#define MAIN_THREADS 512
#define FSTR   264      // B smem row stride (floats)
#define PSTR   36       // A smem row stride (floats)

// main kernel smem layout (float offsets)
#define S_AX   0
#define S_EX   4096
#define S_EX5  8192
#define S_FB   12288                    // 2 * 32*264
#define S_PB   (12288 + 16896)          // 2 * 128*36
#define S_RS   (S_PB + 9216)
#define MAIN_SMEM_BYTES ((S_RS + 128) * 4)

// h-gemm smem layout (float offsets): A hi/lo 128x36, B hi/lo 32x264
#define H_AH 0
#define H_AL 4608
#define H_BH 9216
#define H_BL 17664
#define H_SMEM_BYTES (26112 * 4)

// ---------------- device scratch -------------------------------------------
__device__ float g_h[(size_t)NB * NN * DDIM];   // h = feat@W, tf32-rounded
__device__ float g_wa1[DDIM], g_wa2[DDIM];
__device__ float g_Ax[NB * NN],  g_Ay[NB * NN];
__device__ float g_exj[NB * NN], g_exj5[NB * NN];
__device__ float g_eyi[NB * NN], g_eyi5[NB * NN];

__device__ __forceinline__ float tf32r(float x) {
    unsigned int u;
    asm("cvt.rna.tf32.f32 %0, %1;" : "=r"(u) : "f"(x));
    return __uint_as_float(u);
}
__device__ __forceinline__ void mma8(float* c,
        unsigned int a0, unsigned int a1, unsigned int a2, unsigned int a3,
        unsigned int b0, unsigned int b1) {
    asm volatile(
      "mma.sync.aligned.m16n8k8.row.col.f32.tf32.tf32.f32 "
      "{%0,%1,%2,%3}, {%4,%5,%6,%7}, {%8,%9}, {%0,%1,%2,%3};\n"
      : "+f"(c[0]), "+f"(c[1]), "+f"(c[2]), "+f"(c[3])
      : "r"(a0), "r"(a1), "r"(a2), "r"(a3), "r"(b0), "r"(b1));
}
__device__ __forceinline__ float elu(float v) {
    return (v > 0.f) ? v : (expf(v) - 1.0f);
}

// ---------------- K1: wa1 = W@a1, wa2 = W@a2 --------------------------------
__global__ void prep_w_kernel(const float* __restrict__ W,
                              const float* __restrict__ a1,
                              const float* __restrict__ a2) {
    int r = blockIdx.x, j = threadIdx.x;
    float w  = W[r * DDIM + j];
    float p1 = w * a1[j], p2 = w * a2[j];
    #pragma unroll
    for (int o = 16; o; o >>= 1) {
        p1 += __shfl_xor_sync(0xffffffffu, p1, o);
        p2 += __shfl_xor_sync(0xffffffffu, p2, o);
    }
    __shared__ float s1[8], s2[8];
    if ((j & 31) == 0) { s1[j >> 5] = p1; s2[j >> 5] = p2; }
    __syncthreads();
    if (j == 0) {
        float t1 = 0.f, t2 = 0.f;
        #pragma unroll
        for (int k = 0; k < 8; k++) { t1 += s1[k]; t2 += s2[k]; }
        g_wa1[r] = t1; g_wa2[r] = t2;
    }
}

// ---------------- K2: Ax/Ay dots + exp tables -------------------------------
__global__ void prep_nodes_kernel(const float* __restrict__ feat) {
    __shared__ float w1s[DDIM], w2s[DDIM];
    int tid = threadIdx.x;
    if (tid < DDIM) { w1s[tid] = g_wa1[tid]; w2s[tid] = g_wa2[tid]; }
    __syncthreads();
    int row = blockIdx.x * 8 + (tid >> 5), ln = tid & 31;
    size_t base = ((size_t)row << 8) + ln * 8;
    float4 v0 = *(const float4*)(feat + base);
    float4 v1 = *(const float4*)(feat + base + 4);
    const float* w1 = w1s + ln * 8;
    const float* w2 = w2s + ln * 8;
    float s1 = v0.x*w1[0]+v0.y*w1[1]+v0.z*w1[2]+v0.w*w1[3]
             + v1.x*w1[4]+v1.y*w1[5]+v1.z*w1[6]+v1.w*w1[7];
    float s2 = v0.x*w2[0]+v0.y*w2[1]+v0.z*w2[2]+v0.w*w2[3]
             + v1.x*w2[4]+v1.y*w2[5]+v1.z*w2[6]+v1.w*w2[7];
    #pragma unroll
    for (int o = 16; o; o >>= 1) {
        s1 += __shfl_xor_sync(0xffffffffu, s1, o);
        s2 += __shfl_xor_sync(0xffffffffu, s2, o);
    }
    if (ln == 0) {
        g_Ax[row] = s1; g_exj[row] = expf(s1); g_exj5[row] = expf(ALPHA * s1);
        g_Ay[row] = s2; g_eyi[row] = expf(s2); g_eyi5[row] = expf(ALPHA * s2);
    }
}

// ---------------- K3: h = feat@W  (tf32x3) ----------------------------------
__global__ __launch_bounds__(512, 1)
void h_gemm_kernel(const float* __restrict__ feat, const float* __restrict__ W) {
    extern __shared__ float sm[];
    int tid = threadIdx.x, wrp = tid >> 5, lane = tid & 31;
    int R0 = blockIdx.x * IT;                 // 128 CTAs x 128 rows = 16384
    int g = lane >> 2, tg = lane & 3;
    int mw = (wrp & 1) * 64, nb = (wrp >> 1) * 32;
    int r = tid >> 2, cg = tid & 3;

    float acc[4][4][4];
    #pragma unroll
    for (int mt = 0; mt < 4; mt++)
        #pragma unroll
        for (int nt = 0; nt < 4; nt++)
            #pragma unroll
            for (int q = 0; q < 4; q++) acc[mt][nt][q] = 0.f;

    for (int c = 0; c < 8; c++) {             // K = 256 in 8 chunks of 32
        int k0 = c * JT;
        __syncthreads();
        {   // stage A (feat rows, hi/lo split)
            size_t s = (((size_t)(R0 + r)) << 8) + k0 + cg * 8;
            float4 v0 = *(const float4*)(feat + s);
            float4 v1 = *(const float4*)(feat + s + 4);
            float* ah = sm + H_AH + r * PSTR + cg * 8;
            float* al = sm + H_AL + r * PSTR + cg * 8;
            float hv[8], lv[8];
            const float* vp = (const float*)&v0;
            #pragma unroll
            for (int q = 0; q < 8; q++) {
                float v = (q < 4) ? vp[q] : ((const float*)&v1)[q - 4];
                hv[q] = tf32r(v); lv[q] = tf32r(v - hv[q]);
            }
            *(float4*)(ah)     = make_float4(hv[0], hv[1], hv[2], hv[3]);
            *(float4*)(ah + 4) = make_float4(hv[4], hv[5], hv[6], hv[7]);
            *(float4*)(al)     = make_float4(lv[0], lv[1], lv[2], lv[3]);
            *(float4*)(al + 4) = make_float4(lv[4], lv[5], lv[6], lv[7]);
        }
        {   // stage B (W chunk [32 x 256], hi/lo split)
            #pragma unroll
            for (int k = 0; k < 4; k++) {
                int f = tid + k * 512, rowk = f >> 6, col = (f & 63) << 2;
                float4 v = *(const float4*)(W + (size_t)(k0 + rowk) * DDIM + col);
                float4 h, l;
                h.x = tf32r(v.x); l.x = tf32r(v.x - h.x);
                h.y = tf32r(v.y); l.y = tf32r(v.y - h.y);
                h.z = tf32r(v.z); l.z = tf32r(v.z - h.z);
                h.w = tf32r(v.w); l.w = tf32r(v.w - h.w);
                *(float4*)(sm + H_BH + rowk * FSTR + col) = h;
                *(float4*)(sm + H_BL + rowk * FSTR + col) = l;
            }
        }
        __syncthreads();
        #pragma unroll
        for (int ks = 0; ks < 4; ks++) {
            unsigned int BH0[4], BH1[4], BL0[4], BL1[4];
            const unsigned int* bh = (const unsigned int*)
                (sm + H_BH + (ks * 8 + tg) * FSTR + nb + g);
            const unsigned int* bl = (const unsigned int*)
                (sm + H_BL + (ks * 8 + tg) * FSTR + nb + g);
            #pragma unroll
            for (int nt = 0; nt < 4; nt++) {
                BH0[nt] = bh[nt * 8]; BH1[nt] = bh[nt * 8 + 4 * FSTR];
                BL0[nt] = bl[nt * 8]; BL1[nt] = bl[nt * 8 + 4 * FSTR];
            }
            #pragma unroll
            for (int mt = 0; mt < 4; mt++) {
                const unsigned int* pah = (const unsigned int*)
                    (sm + H_AH + (mw + mt * 16 + g) * PSTR + ks * 8 + tg);
                const unsigned int* pal = (const unsigned int*)
                    (sm + H_AL + (mw + mt * 16 + g) * PSTR + ks * 8 + tg);
                unsigned int ah0 = pah[0], ah1 = pah[8 * PSTR];
                unsigned int ah2 = pah[4], ah3 = pah[8 * PSTR + 4];
                unsigned int al0 = pal[0], al1 = pal[8 * PSTR];
                unsigned int al2 = pal[4], al3 = pal[8 * PSTR + 4];
                #pragma unroll
                for (int nt = 0; nt < 4; nt++) {
                    mma8(acc[mt][nt], ah0, ah1, ah2, ah3, BH0[nt], BH1[nt]);
                    mma8(acc[mt][nt], ah0, ah1, ah2, ah3, BL0[nt], BL1[nt]);
                    mma8(acc[mt][nt], al0, al1, al2, al3, BH0[nt], BH1[nt]);
                }
            }
        }
    }
    // store h (tf32-rounded)
    #pragma unroll
    for (int mt = 0; mt < 4; mt++) {
        float* o0 = g_h + (size_t)(R0 + mw + mt * 16 + g) * DDIM;
        float* o1 = o0 + 8 * DDIM;
        #pragma unroll
        for (int nt = 0; nt < 4; nt++) {
            int col = nb + nt * 8 + tg * 2;
            *(float2*)(o0 + col) = make_float2(tf32r(acc[mt][nt][0]),
                                               tf32r(acc[mt][nt][1]));
            *(float2*)(o1 + col) = make_float2(tf32r(acc[mt][nt][2]),
                                               tf32r(acc[mt][nt][3]));
        }
    }
}

// ---------------- K4: main fused kernel — P gen + P@h + ELU epilogue --------
__global__ __launch_bounds__(MAIN_THREADS, 1)
void gat_main_kernel(const int* __restrict__ adj, float* __restrict__ out) {
    extern __shared__ float sm[];
    int tid  = threadIdx.x;
    int b    = blockIdx.x >> 5;
    int i0   = (blockIdx.x & 31) * IT;
    int wrp  = tid >> 5, lane = tid & 31;

    {   // preload j-side tables for this batch
        const float* pax = g_Ax   + b * NN;
        const float* pex = g_exj  + b * NN;
        const float* pe5 = g_exj5 + b * NN;
        for (int i = tid; i < NN; i += MAIN_THREADS) {
            sm[S_AX + i] = pax[i]; sm[S_EX + i] = pex[i]; sm[S_EX5 + i] = pe5[i];
        }
    }
    int r  = tid >> 2, cg = tid & 3;
    float rAy = g_Ay  [b * NN + i0 + r];
    float rey = g_eyi [b * NN + i0 + r];
    float re5 = g_eyi5[b * NN + i0 + r];
    const int*   adjbase = adj + (((size_t)(b * NN + i0 + r)) << 12) + cg * 8;
    const float* hbase   = g_h + (size_t)b * NN * DDIM;

    float acc[4][4][4];
    #pragma unroll
    for (int mt = 0; mt < 4; mt++)
        #pragma unroll
        for (int nt = 0; nt < 4; nt++)
            #pragma unroll
            for (int q = 0; q < 4; q++) acc[mt][nt][q] = 0.f;
    float rsum = 0.f;
    float4 fr[4];
    int4   ar[2];
    int g = lane >> 2, tg = lane & 3;
    int mw = (wrp & 1) * 64, nb = (wrp >> 1) * 32;

#define LOADG(c) do {                                                          \
        int j0_ = (c) * JT;                                                    \
        const float4* src_ = (const float4*)(hbase + (size_t)j0_ * DDIM);      \
        fr[0] = src_[tid];                                                     \
        fr[1] = src_[tid +     MAIN_THREADS];                                  \
        fr[2] = src_[tid + 2 * MAIN_THREADS];                                  \
        fr[3] = src_[tid + 3 * MAIN_THREADS];                                  \
        const int4* ap_ = (const int4*)(adjbase + j0_);                        \
        ar[0] = ap_[0]; ar[1] = ap_[1];                                        \
    } while (0)

#define GENP(c, buf) do {                                                      \
        int j0_ = (c) * JT;                                                    \
        float pq_[8];                                                          \
        _Pragma("unroll")                                                      \
        for (int q = 0; q < 8; q++) {                                          \
            int av_ = (q < 4) ? ((const int*)&ar[0])[q]                        \
                              : ((const int*)&ar[1])[q - 4];                   \
            int j_  = j0_ + cg * 8 + q;                                        \
            float lg_ = sm[S_AX + j_] + rAy;                                   \
            float e_  = (lg_ > 0.f) ? sm[S_EX + j_] * rey                      \
                                    : sm[S_EX5 + j_] * re5;                    \
            float p_  = (av_ > 0) ? e_ : 0.f;                                  \
            p_ = tf32r(p_);                                                    \
            pq_[q] = p_; rsum += p_;                                           \
        }                                                                      \
        float* pb_ = sm + S_PB + (buf) * (IT * PSTR) + r * PSTR + cg * 8;      \
        *(float4*)(pb_)     = make_float4(pq_[0], pq_[1], pq_[2], pq_[3]);     \
        *(float4*)(pb_ + 4) = make_float4(pq_[4], pq_[5], pq_[6], pq_[7]);     \
        float* fb_ = sm + S_FB + (buf) * (JT * FSTR);                          \
        _Pragma("unroll")                                                      \
        for (int k = 0; k < 4; k++) {                                          \
            int f_ = tid + k * MAIN_THREADS;                                   \
            *(float4*)(fb_ + (f_ >> 6) * FSTR + ((f_ & 63) << 2)) = fr[k];     \
        }                                                                      \
    } while (0)

#define MMACHUNK(buf) do {                                                     \
        const float* pbF_ = sm + S_PB + (buf) * (IT * PSTR);                   \
        const float* fbF_ = sm + S_FB + (buf) * (JT * FSTR);                   \
        _Pragma("unroll")                                                      \
        for (int ks = 0; ks < 4; ks++) {                                       \
            unsigned int B0_[4], B1_[4];                                       \
            const unsigned int* pbb_ = (const unsigned int*)                   \
                (fbF_ + (ks * 8 + tg) * FSTR + nb + g);                        \
            _Pragma("unroll")                                                  \
            for (int nt = 0; nt < 4; nt++) {                                   \
                B0_[nt] = pbb_[nt * 8];                                        \
                B1_[nt] = pbb_[nt * 8 + 4 * FSTR];                             \
            }                                                                  \
            _Pragma("unroll")                                                  \
            for (int mt = 0; mt < 4; mt++) {                                   \
                const unsigned int* pa_ = (const unsigned int*)                \
                    (pbF_ + (mw + mt * 16 + g) * PSTR + ks * 8 + tg);          \
                unsigned int a0_ = pa_[0], a1_ = pa_[8 * PSTR];                \
                unsigned int a2_ = pa_[4], a3_ = pa_[8 * PSTR + 4];            \
                _Pragma("unroll")                                              \
                for (int nt = 0; nt < 4; nt++)                                 \
                    mma8(acc[mt][nt], a0_, a1_, a2_, a3_, B0_[nt], B1_[nt]);   \
            }                                                                  \
        }                                                                      \
    } while (0)

    LOADG(0);
    GENP(0, 0);
    __syncthreads();
    for (int c = 0; c < NCHUNK; c++) {
        int cur = c & 1;
        if (c + 1 < NCHUNK) LOADG(c + 1);
        MMACHUNK(cur);
        if (c + 1 < NCHUNK) GENP(c + 1, cur ^ 1);
        __syncthreads();
    }
#undef LOADG
#undef GENP
#undef MMACHUNK

    // rowsum reduce (4 threads per row share rsum)
    rsum += __shfl_xor_sync(0xffffffffu, rsum, 1);
    rsum += __shfl_xor_sync(0xffffffffu, rsum, 2);
    if (cg == 0) sm[S_RS + r] = 1.0f / rsum;
    __syncthreads();

    // fused epilogue: scale + ELU + store out
    #pragma unroll
    for (int mt = 0; mt < 4; mt++) {
        int rloc = mw + mt * 16 + g;
        float inv0 = sm[S_RS + rloc];
        float inv1 = sm[S_RS + rloc + 8];
        float* o0 = out + (size_t)(b * NN + i0 + rloc) * DDIM;
        float* o1 = o0 + 8 * DDIM;
        #pragma unroll
        for (int nt = 0; nt < 4; nt++) {
            int col = nb + nt * 8 + tg * 2;
            *(float2*)(o0 + col) = make_float2(elu(acc[mt][nt][0] * inv0),
                                               elu(acc[mt][nt][1] * inv0));
            *(float2*)(o1 + col) = make_float2(elu(acc[mt][nt][2] * inv1),
                                               elu(acc[mt][nt][3] * inv1));
        }
    }
}

// ---------------------------------------------------------------------------
extern "C" void kernel_launch(void* const* d_in, const int* in_sizes, int n_in,
                              void* d_out, int out_size) {
    const float* feat = (const float*)d_in[0];
    const int*   adj  = (const int*)d_in[1];
    const float* W    = (const float*)d_in[2];
    const float* a1   = (const float*)d_in[3];
    const float* a2   = (const float*)d_in[4];
    float* out = (float*)d_out;

    cudaFuncSetAttribute(gat_main_kernel,
                         cudaFuncAttributeMaxDynamicSharedMemorySize,
                         MAIN_SMEM_BYTES);
    cudaFuncSetAttribute(h_gemm_kernel,
                         cudaFuncAttributeMaxDynamicSharedMemorySize,
                         H_SMEM_BYTES);

    prep_w_kernel    <<<256, 256>>>(W, a1, a2);
    prep_nodes_kernel<<<2048, 256>>>(feat);
    h_gemm_kernel    <<<(NB * NN) / IT, 512, H_SMEM_BYTES>>>(feat, W);
    gat_main_kernel  <<<NB * (NN / IT), MAIN_THREADS, MAIN_SMEM_BYTES>>>(adj, out);
    (void)in_sizes; (void)n_in; (void)out_size;
}

// round 13
// speedup vs baseline: 1.9464x; 1.1167x over previous
#include <cuda_runtime.h>
#include <cstdint>
#include <math.h>

// ---------------------------------------------------------------------------
// GAT layer (B=4, N=4096, D=256) — legacy tf32 mma, occupancy-2 main kernel
//   wa1=W@a1, wa2=W@a2; Ax=feat@wa1, Ay=feat@wa2 (fp32 exact)
//   h = feat@W   (tf32x3 tensor GEMM, ~fp32 accurate, stored tf32)
//   P[i,j] = adj ? (Ax[j]+Ay[i]>0 ? e^Ax[j]e^Ay[i] : e^{.2Ax[j]}e^{.2Ay[i]}) : 0
//   out = ELU( (P @ h) / rowsum(P) )   (tf32 mma, fused epilogue)
// ---------------------------------------------------------------------------

#define ALPHA  0.2f
#define NB     4
#define NN     4096
#define DDIM   256
#define IT     64                  // i-rows per CTA (occ 2)
#define JT     32
#define NCHUNK (NN / JT)
#define MT     256                 // main kernel threads
#define FSTR   264                 // B smem row stride (floats)
#define PSTR   36                  // A smem row stride (floats)

// h-gemm smem layout (float offsets)
#define H_AH 0
#define H_AL 4608
#define H_BH 9216
#define H_BL 17664
#define H_SMEM_BYTES (26112 * 4)

// main kernel smem layout (BYTE offsets)
#define FBO   0                       // h double buffer 2 x 32x264x4 = 67584
#define FBSZ  33792
#define PBO   67584                   // P double buffer 2 x 64x36x4 = 18432
#define PBSZ  9216
#define T4O   86016                   // t4 stage 2 x 576 B
#define RSO   87168                   // float[64] 1/rowsum
#define MAIN_SMEM_BYTES 87424

// ---------------- device scratch -------------------------------------------
__device__ float  g_h[(size_t)NB * NN * DDIM];  // h = feat@W, tf32-rounded
__device__ float4 g_t4[NB * NN];                // (Ax, e^Ax, e^.2Ax, 0)
__device__ float  g_wa1[DDIM], g_wa2[DDIM];
__device__ float  g_Ay[NB * NN], g_eyi[NB * NN], g_eyi5[NB * NN];

// ---------------- helpers ---------------------------------------------------
__device__ __forceinline__ float tf32r(float x) {
    unsigned int u;
    asm("cvt.rna.tf32.f32 %0, %1;" : "=r"(u) : "f"(x));
    return __uint_as_float(u);
}
__device__ __forceinline__ uint32_t s2u(const void* p) {
    uint32_t a;
    asm("{ .reg .u64 t; cvta.to.shared.u64 t, %1; cvt.u32.u64 %0, t; }"
        : "=r"(a) : "l"(p));
    return a;
}
__device__ __forceinline__ void cpa16(uint32_t dst, const void* src) {
    asm volatile("cp.async.cg.shared.global [%0], [%1], 16;"
                 :: "r"(dst), "l"(src) : "memory");
}
#define CPACOMMIT() asm volatile("cp.async.commit_group;" ::: "memory")
#define CPAWAIT0()  asm volatile("cp.async.wait_group 0;" ::: "memory")
__device__ __forceinline__ void mma8(float* c,
        unsigned int a0, unsigned int a1, unsigned int a2, unsigned int a3,
        unsigned int b0, unsigned int b1) {
    asm volatile(
      "mma.sync.aligned.m16n8k8.row.col.f32.tf32.tf32.f32 "
      "{%0,%1,%2,%3}, {%4,%5,%6,%7}, {%8,%9}, {%0,%1,%2,%3};\n"
      : "+f"(c[0]), "+f"(c[1]), "+f"(c[2]), "+f"(c[3])
      : "r"(a0), "r"(a1), "r"(a2), "r"(a3), "r"(b0), "r"(b1));
}
__device__ __forceinline__ float elu(float v) {
    return (v > 0.f) ? v : (expf(v) - 1.0f);
}

// ---------------- K1: wa1 = W@a1, wa2 = W@a2 --------------------------------
__global__ void prep_w_kernel(const float* __restrict__ W,
                              const float* __restrict__ a1,
                              const float* __restrict__ a2) {
    int r = blockIdx.x, j = threadIdx.x;
    float w  = W[r * DDIM + j];
    float p1 = w * a1[j], p2 = w * a2[j];
    #pragma unroll
    for (int o = 16; o; o >>= 1) {
        p1 += __shfl_xor_sync(0xffffffffu, p1, o);
        p2 += __shfl_xor_sync(0xffffffffu, p2, o);
    }
    __shared__ float s1[8], s2[8];
    if ((j & 31) == 0) { s1[j >> 5] = p1; s2[j >> 5] = p2; }
    __syncthreads();
    if (j == 0) {
        float t1 = 0.f, t2 = 0.f;
        #pragma unroll
        for (int k = 0; k < 8; k++) { t1 += s1[k]; t2 += s2[k]; }
        g_wa1[r] = t1; g_wa2[r] = t2;
    }
}

// ---------------- K2: Ax/Ay dots + fused exp table --------------------------
__global__ void prep_nodes_kernel(const float* __restrict__ feat) {
    __shared__ float w1s[DDIM], w2s[DDIM];
    int tid = threadIdx.x;
    if (tid < DDIM) { w1s[tid] = g_wa1[tid]; w2s[tid] = g_wa2[tid]; }
    __syncthreads();
    int row = blockIdx.x * 8 + (tid >> 5), ln = tid & 31;
    size_t base = ((size_t)row << 8) + ln * 8;
    float4 v0 = *(const float4*)(feat + base);
    float4 v1 = *(const float4*)(feat + base + 4);
    const float* w1 = w1s + ln * 8;
    const float* w2 = w2s + ln * 8;
    float s1 = v0.x*w1[0]+v0.y*w1[1]+v0.z*w1[2]+v0.w*w1[3]
             + v1.x*w1[4]+v1.y*w1[5]+v1.z*w1[6]+v1.w*w1[7];
    float s2 = v0.x*w2[0]+v0.y*w2[1]+v0.z*w2[2]+v0.w*w2[3]
             + v1.x*w2[4]+v1.y*w2[5]+v1.z*w2[6]+v1.w*w2[7];
    #pragma unroll
    for (int o = 16; o; o >>= 1) {
        s1 += __shfl_xor_sync(0xffffffffu, s1, o);
        s2 += __shfl_xor_sync(0xffffffffu, s2, o);
    }
    if (ln == 0) {
        g_t4[row] = make_float4(s1, expf(s1), expf(ALPHA * s1), 0.f);
        g_Ay[row] = s2; g_eyi[row] = expf(s2); g_eyi5[row] = expf(ALPHA * s2);
    }
}

// ---------------- K3: h = feat@W  (tf32x3, proven R8) ----------------------
__global__ __launch_bounds__(512, 1)
void h_gemm_kernel(const float* __restrict__ feat, const float* __restrict__ W) {
    extern __shared__ float sm[];
    int tid = threadIdx.x, wrp = tid >> 5, lane = tid & 31;
    int R0 = blockIdx.x * 128;
    int g = lane >> 2, tg = lane & 3;
    int mw = (wrp & 1) * 64, nb = (wrp >> 1) * 32;
    int r = tid >> 2, cg = tid & 3;

    float acc[4][4][4];
    #pragma unroll
    for (int mt = 0; mt < 4; mt++)
        #pragma unroll
        for (int nt = 0; nt < 4; nt++)
            #pragma unroll
            for (int q = 0; q < 4; q++) acc[mt][nt][q] = 0.f;

    for (int c = 0; c < 8; c++) {
        int k0 = c * JT;
        __syncthreads();
        {   // stage A (feat rows, hi/lo)
            size_t s = (((size_t)(R0 + r)) << 8) + k0 + cg * 8;
            float4 v0 = *(const float4*)(feat + s);
            float4 v1 = *(const float4*)(feat + s + 4);
            float* ah = sm + H_AH + r * PSTR + cg * 8;
            float* al = sm + H_AL + r * PSTR + cg * 8;
            float hv[8], lv[8];
            #pragma unroll
            for (int q = 0; q < 8; q++) {
                float v = (q < 4) ? ((const float*)&v0)[q] : ((const float*)&v1)[q - 4];
                hv[q] = tf32r(v); lv[q] = tf32r(v - hv[q]);
            }
            *(float4*)(ah)     = make_float4(hv[0], hv[1], hv[2], hv[3]);
            *(float4*)(ah + 4) = make_float4(hv[4], hv[5], hv[6], hv[7]);
            *(float4*)(al)     = make_float4(lv[0], lv[1], lv[2], lv[3]);
            *(float4*)(al + 4) = make_float4(lv[4], lv[5], lv[6], lv[7]);
        }
        {   // stage B (W chunk, hi/lo)
            #pragma unroll
            for (int k = 0; k < 4; k++) {
                int f = tid + k * 512, rowk = f >> 6, col = (f & 63) << 2;
                float4 v = *(const float4*)(W + (size_t)(k0 + rowk) * DDIM + col);
                float4 h, l;
                h.x = tf32r(v.x); l.x = tf32r(v.x - h.x);
                h.y = tf32r(v.y); l.y = tf32r(v.y - h.y);
                h.z = tf32r(v.z); l.z = tf32r(v.z - h.z);
                h.w = tf32r(v.w); l.w = tf32r(v.w - h.w);
                *(float4*)(sm + H_BH + rowk * FSTR + col) = h;
                *(float4*)(sm + H_BL + rowk * FSTR + col) = l;
            }
        }
        __syncthreads();
        #pragma unroll
        for (int ks = 0; ks < 4; ks++) {
            unsigned int BH0[4], BH1[4], BL0[4], BL1[4];
            const unsigned int* bh = (const unsigned int*)
                (sm + H_BH + (ks * 8 + tg) * FSTR + nb + g);
            const unsigned int* bl = (const unsigned int*)
                (sm + H_BL + (ks * 8 + tg) * FSTR + nb + g);
            #pragma unroll
            for (int nt = 0; nt < 4; nt++) {
                BH0[nt] = bh[nt * 8]; BH1[nt] = bh[nt * 8 + 4 * FSTR];
                BL0[nt] = bl[nt * 8]; BL1[nt] = bl[nt * 8 + 4 * FSTR];
            }
            #pragma unroll
            for (int mt = 0; mt < 4; mt++) {
                const unsigned int* pah = (const unsigned int*)
                    (sm + H_AH + (mw + mt * 16 + g) * PSTR + ks * 8 + tg);
                const unsigned int* pal = (const unsigned int*)
                    (sm + H_AL + (mw + mt * 16 + g) * PSTR + ks * 8 + tg);
                unsigned int ah0 = pah[0], ah1 = pah[8 * PSTR];
                unsigned int ah2 = pah[4], ah3 = pah[8 * PSTR + 4];
                unsigned int al0 = pal[0], al1 = pal[8 * PSTR];
                unsigned int al2 = pal[4], al3 = pal[8 * PSTR + 4];
                #pragma unroll
                for (int nt = 0; nt < 4; nt++) {
                    mma8(acc[mt][nt], ah0, ah1, ah2, ah3, BH0[nt], BH1[nt]);
                    mma8(acc[mt][nt], ah0, ah1, ah2, ah3, BL0[nt], BL1[nt]);
                    mma8(acc[mt][nt], al0, al1, al2, al3, BH0[nt], BH1[nt]);
                }
            }
        }
    }
    // store h (tf32-rounded)
    #pragma unroll
    for (int mt = 0; mt < 4; mt++) {
        float* o0 = g_h + (size_t)(R0 + mw + mt * 16 + g) * DDIM;
        float* o1 = o0 + 8 * DDIM;
        #pragma unroll
        for (int nt = 0; nt < 4; nt++) {
            int col = nb + nt * 8 + tg * 2;
            *(float2*)(o0 + col) = make_float2(tf32r(acc[mt][nt][0]),
                                               tf32r(acc[mt][nt][1]));
            *(float2*)(o1 + col) = make_float2(tf32r(acc[mt][nt][2]),
                                               tf32r(acc[mt][nt][3]));
        }
    }
}

// ---------------- K4: main kernel — occ 2, cp.async staging -----------------
__global__ __launch_bounds__(MT, 2)
void gat_main_kernel(const int* __restrict__ adj, float* __restrict__ out) {
    extern __shared__ float sm[];
    char* smc = (char*)sm;
    uint32_t sb = s2u(sm);
    int tid  = threadIdx.x;
    int b    = blockIdx.x >> 6;            // 64 CTAs per batch
    int i0   = (blockIdx.x & 63) * IT;
    int wrp  = tid >> 5, lane = tid & 31;
    int g = lane >> 2, tg = lane & 3;
    int mw = (wrp & 1) * 32, nb = (wrp >> 1) * 64;   // warp tile m32 x n64
    int r = tid >> 2, cg = tid & 3;

    float rAy = g_Ay  [b * NN + i0 + r];
    float rey = g_eyi [b * NN + i0 + r];
    float re5 = g_eyi5[b * NN + i0 + r];
    const int*    adjrow = adj + (((size_t)(b * NN + i0 + r)) << 12) + cg * 8;
    const float*  hbase  = g_h  + ((size_t)b << 20);
    const float4* t4g    = g_t4 + b * NN;

    float acc[2][8][4];
    #pragma unroll
    for (int mt = 0; mt < 2; mt++)
        #pragma unroll
        for (int nt = 0; nt < 8; nt++)
            #pragma unroll
            for (int q = 0; q < 4; q++) acc[mt][nt][q] = 0.f;
    float rsum = 0.f;
    int4 ar0, ar1;

#define STAGE_H(c, buf) do {                                                   \
        const float* hsrc_ = hbase + (size_t)(c) * JT * DDIM;                  \
        uint32_t fb_ = sb + FBO + (buf) * FBSZ;                                \
        _Pragma("unroll")                                                      \
        for (int k = 0; k < 8; k++) {                                          \
            int f_ = tid + k * MT;                                             \
            cpa16(fb_ + (f_ >> 6) * (FSTR * 4) + ((f_ & 63) << 4),             \
                  hsrc_ + ((f_ >> 6) << 8) + ((f_ & 63) << 2));                \
        }                                                                      \
    } while (0)

#define STAGE_T4(c, slot) do {                                                 \
        if (tid < 32) {                                                        \
            cpa16(sb + T4O + (slot) * 576 +                                    \
                      (((tid >> 3) * 9 + (tid & 7)) << 4),                     \
                  t4g + (c) * JT + tid);                                       \
        }                                                                      \
    } while (0)

#define GENP(c, buf, slot) do {                                                \
        const float4* t4s_ = (const float4*)(smc + T4O + (slot) * 576);        \
        float pq_[8];                                                          \
        _Pragma("unroll")                                                      \
        for (int q = 0; q < 8; q++) {                                          \
            int av_ = (q < 4) ? ((const int*)&ar0)[q]                          \
                              : ((const int*)&ar1)[q - 4];                     \
            float4 t_ = t4s_[cg * 9 + q];                                      \
            float lg_ = t_.x + rAy;                                            \
            float e_  = (lg_ > 0.f) ? t_.y * rey : t_.z * re5;                 \
            float p_  = (av_ > 0) ? tf32r(e_) : 0.f;                           \
            pq_[q] = p_; rsum += p_;                                           \
        }                                                                      \
        float* pb_ = (float*)(smc + PBO + (buf) * PBSZ) + r * PSTR + cg * 8;   \
        *(float4*)(pb_)     = make_float4(pq_[0], pq_[1], pq_[2], pq_[3]);     \
        *(float4*)(pb_ + 4) = make_float4(pq_[4], pq_[5], pq_[6], pq_[7]);     \
    } while (0)

#define MMACHUNK(buf) do {                                                     \
        const float* pbF_ = (const float*)(smc + PBO + (buf) * PBSZ);          \
        const float* fbF_ = (const float*)(smc + FBO + (buf) * FBSZ);          \
        _Pragma("unroll")                                                      \
        for (int ks = 0; ks < 4; ks++) {                                       \
            unsigned int B0_[8], B1_[8];                                       \
            const unsigned int* pbb_ = (const unsigned int*)                   \
                (fbF_ + (ks * 8 + tg) * FSTR + nb + g);                        \
            _Pragma("unroll")                                                  \
            for (int nt = 0; nt < 8; nt++) {                                   \
                B0_[nt] = pbb_[nt * 8];                                        \
                B1_[nt] = pbb_[nt * 8 + 4 * FSTR];                             \
            }                                                                  \
            _Pragma("unroll")                                                  \
            for (int mt = 0; mt < 2; mt++) {                                   \
                const unsigned int* pa_ = (const unsigned int*)                \
                    (pbF_ + (mw + mt * 16 + g) * PSTR + ks * 8 + tg);          \
                unsigned int a0_ = pa_[0], a1_ = pa_[8 * PSTR];                \
                unsigned int a2_ = pa_[4], a3_ = pa_[8 * PSTR + 4];            \
                _Pragma("unroll")                                              \
                for (int nt = 0; nt < 8; nt++)                                 \
                    mma8(acc[mt][nt], a0_, a1_, a2_, a3_, B0_[nt], B1_[nt]);   \
            }                                                                  \
        }                                                                      \
    } while (0)

    // ---- prologue: stage h(0), t4(0), t4(1); gen P(0) ----
    STAGE_H(0, 0);
    STAGE_T4(0, 0);
    STAGE_T4(1, 1);
    CPACOMMIT();
    ar0 = *(const int4*)(adjrow);
    ar1 = *(const int4*)(adjrow + 4);
    CPAWAIT0();
    __syncthreads();
    GENP(0, 0, 0);
    __syncthreads();

    // ---- mainloop ----
    for (int c = 0; c < NCHUNK; c++) {
        int buf = c & 1;
        if (c + 1 < NCHUNK) {
            STAGE_H(c + 1, buf ^ 1);
            int j0n = (c + 1) * JT;
            ar0 = *(const int4*)(adjrow + j0n);
            ar1 = *(const int4*)(adjrow + j0n + 4);
        }
        if (c + 2 < NCHUNK) STAGE_T4(c + 2, c & 1);
        CPACOMMIT();
        MMACHUNK(buf);
        if (c + 1 < NCHUNK) GENP(c + 1, buf ^ 1, (c + 1) & 1);
        CPAWAIT0();
        __syncthreads();
    }
#undef STAGE_H
#undef STAGE_T4
#undef GENP
#undef MMACHUNK

    // ---- rowsum reduce (4 adjacent lanes per row) ----
    rsum += __shfl_xor_sync(0xffffffffu, rsum, 1);
    rsum += __shfl_xor_sync(0xffffffffu, rsum, 2);
    float* rs = (float*)(smc + RSO);
    if (cg == 0) rs[r] = 1.0f / rsum;
    __syncthreads();

    // ---- fused epilogue: scale + ELU + store ----
    #pragma unroll
    for (int mt = 0; mt < 2; mt++) {
        int rloc = mw + mt * 16 + g;
        float inv0 = rs[rloc];
        float inv1 = rs[rloc + 8];
        float* o0 = out + (size_t)(b * NN + i0 + rloc) * DDIM;
        float* o1 = o0 + 8 * DDIM;
        #pragma unroll
        for (int nt = 0; nt < 8; nt++) {
            int col = nb + nt * 8 + tg * 2;
            *(float2*)(o0 + col) = make_float2(elu(acc[mt][nt][0] * inv0),
                                               elu(acc[mt][nt][1] * inv0));
            *(float2*)(o1 + col) = make_float2(elu(acc[mt][nt][2] * inv1),
                                               elu(acc[mt][nt][3] * inv1));
        }
    }
}

// ---------------------------------------------------------------------------
extern "C" void kernel_launch(void* const* d_in, const int* in_sizes, int n_in,
                              void* d_out, int out_size) {
    const float* feat = (const float*)d_in[0];
    const int*   adj  = (const int*)d_in[1];
    const float* W    = (const float*)d_in[2];
    const float* a1   = (const float*)d_in[3];
    const float* a2   = (const float*)d_in[4];
    float* out = (float*)d_out;

    cudaFuncSetAttribute(h_gemm_kernel,
                         cudaFuncAttributeMaxDynamicSharedMemorySize,
                         H_SMEM_BYTES);
    cudaFuncSetAttribute(gat_main_kernel,
                         cudaFuncAttributeMaxDynamicSharedMemorySize,
                         MAIN_SMEM_BYTES);

    prep_w_kernel    <<<256, 256>>>(W, a1, a2);
    prep_nodes_kernel<<<2048, 256>>>(feat);
    h_gemm_kernel    <<<(NB * NN) / 128, 512, H_SMEM_BYTES>>>(feat, W);
    gat_main_kernel  <<<NB * (NN / IT), MT, MAIN_SMEM_BYTES>>>(adj, out);
    (void)in_sizes; (void)n_in; (void)out_size;
}